// round 15
// baseline (speedup 1.0000x reference)
#include <cuda_runtime.h>
#include <cuda_bf16.h>
#include <cstdint>

// ---------------------------------------------------------------------------
// QuantizedLinear: out = x @ quantize(W)^T + bias
// quantize(w) = clamp(ceil(w - 0.5), -4, 3)  (== jnp argmin, first-index ties)
// W = randn*0.1 -> nonzero quantized entries need |w| >= 5 sigma -> nnz ~ 10.
//
// Two-kernel structure (proven):
//   k_quant:    pure-read stream over W, MLP=4 batched loads (at read cap).
//   k_fill_fix: ONE WAVE (grid=1184, 8/SM). Block owns rows {bid, bid+1184,..}
//               (balanced, no wave-2 tail). Bias staged in 16 KB SMEM once,
//               then TMA bulk stores (cp.async.bulk) write each owned row —
//               async-engine path, probing past the ~5 TB/s STG write cap.
//               After wait_group 0: fixups on owned rows (no races).
//               nnz > NNZ_CAP: per-owned-row dense GEMM safety net.
//               Last-finishing block resets the counter for the next replay.
// ---------------------------------------------------------------------------

#define NNZ_CAP  (1 << 20)   // 1M entries = 8 MB scratch
#define FBLOCKS  1184        // 148 SMs * 8 blocks: exactly one wave
#define NTHREADS 256

__device__ int          g_nnz;               // zero-init; reset by k_fill_fix
__device__ unsigned int g_done;              // ticket for last-block reset
__device__ unsigned int g_eidx[NNZ_CAP];     // o*IN + i
__device__ float        g_eval[NNZ_CAP];     // quantized level (nonzero)

__device__ __forceinline__ float quant1(float w) {
    float q = ceilf(w - 0.5f);               // round-half-down, exact vs argmin
    return fmaxf(-4.0f, fminf(3.0f, q));
}

__device__ __forceinline__ void collect4(float4 w, unsigned base) {
    float q0 = quant1(w.x), q1 = quant1(w.y);
    float q2 = quant1(w.z), q3 = quant1(w.w);
    if ((q0 != 0.f) | (q1 != 0.f) | (q2 != 0.f) | (q3 != 0.f)) {
        if (q0 != 0.f) { int s = atomicAdd(&g_nnz, 1); if (s < NNZ_CAP) { g_eidx[s] = base + 0u; g_eval[s] = q0; } }
        if (q1 != 0.f) { int s = atomicAdd(&g_nnz, 1); if (s < NNZ_CAP) { g_eidx[s] = base + 1u; g_eval[s] = q1; } }
        if (q2 != 0.f) { int s = atomicAdd(&g_nnz, 1); if (s < NNZ_CAP) { g_eidx[s] = base + 2u; g_eval[s] = q2; } }
        if (q3 != 0.f) { int s = atomicAdd(&g_nnz, 1); if (s < NNZ_CAP) { g_eidx[s] = base + 3u; g_eval[s] = q3; } }
    }
}

__device__ __forceinline__ uint32_t smem_u32(const void* p) {
    uint32_t a;
    asm("{ .reg .u64 t; cvta.to.shared.u64 t, %1; cvt.u32.u64 %0, t; }"
        : "=r"(a) : "l"(p));
    return a;
}

// ---- Kernel 1: pure-read quantize + collect, MLP=4 batched loads -----------
__global__ void __launch_bounds__(256, 8)
k_quant(const float* __restrict__ weight, int IN, int OUT) {
    const unsigned Wn = (unsigned)OUT * (unsigned)IN;
    const unsigned W4 = Wn >> 2;
    const unsigned gid = blockIdx.x * blockDim.x + threadIdx.x;
    const unsigned stride = gridDim.x * blockDim.x;
    const float4* w4p = reinterpret_cast<const float4*>(weight);

    unsigned t = gid;
    for (; t + 3u * stride < W4; t += 4u * stride) {
        float4 a = __ldcs(&w4p[t]);
        float4 b = __ldcs(&w4p[t + stride]);
        float4 c = __ldcs(&w4p[t + 2u * stride]);
        float4 d = __ldcs(&w4p[t + 3u * stride]);
        collect4(a, t << 2);
        collect4(b, (t + stride) << 2);
        collect4(c, (t + 2u * stride) << 2);
        collect4(d, (t + 3u * stride) << 2);
    }
    for (; t < W4; t += stride)
        collect4(__ldcs(&w4p[t]), t << 2);

    unsigned tail = Wn & 3u;                 // no-op for 4-divisible shapes
    if (gid < tail) {
        unsigned e = (W4 << 2) + gid;
        float q = quant1(weight[e]);
        if (q != 0.f) { int s = atomicAdd(&g_nnz, 1); if (s < NNZ_CAP) { g_eidx[s] = e; g_eval[s] = q; } }
    }
}

// ---- Kernel 2: one-wave owned-rows TMA fill + fixup ------------------------
// grid = FBLOCKS, block = 256. Block owns rows r = bid + k*FBLOCKS.
__global__ void __launch_bounds__(256, 8)
k_fill_fix(const float* __restrict__ x,
           const float* __restrict__ weight,
           const float* __restrict__ bias,
           float* __restrict__ out,
           int IN, int OUT, int B) {
    __shared__ __align__(128) float s_buf[4096];   // bias row / fallback x-chunk
    const int nnz = g_nnz;
    const int tid = threadIdx.x;
    const int bid = blockIdx.x;
    const int FB  = gridDim.x;
    const int nrows_own = (bid < B) ? ((B - 1 - bid) / FB + 1) : 0;

    if (nnz <= NNZ_CAP) {
        // ---- Phase A: bias fill of owned rows ----
        const bool tma_ok = (OUT > 0) && (OUT <= 4096) && ((OUT & 3) == 0);
        if (tma_ok) {
            for (int t = tid; t < OUT; t += NTHREADS)
                s_buf[t] = __ldg(&bias[t]);
            __syncthreads();
            asm volatile("fence.proxy.async.shared::cta;" ::: "memory");
            if (tid == 0) {
                const uint32_t saddr = smem_u32(s_buf);
                const unsigned bytes = (unsigned)OUT * 4u;
                for (int k = 0; k < nrows_own; k++) {
                    const size_t r = (size_t)bid + (size_t)k * FB;
                    asm volatile(
                        "cp.async.bulk.global.shared::cta.bulk_group [%0], [%1], %2;"
                        :: "l"(out + r * (size_t)OUT), "r"(saddr), "r"(bytes)
                        : "memory");
                }
                asm volatile("cp.async.bulk.commit_group;" ::: "memory");
                asm volatile("cp.async.bulk.wait_group 0;" ::: "memory");
            }
            __syncthreads();                 // TMA writes complete before fixup
        } else {                             // generic STG path
            for (int k = 0; k < nrows_own; k++) {
                const size_t r = (size_t)bid + (size_t)k * FB;
                float* ob = out + r * (size_t)OUT;
                for (int t = tid; t < OUT; t += NTHREADS)
                    ob[t] = __ldg(&bias[t]);
            }
            __syncthreads();
        }

        // ---- Phase B: fixups on owned rows (flattened, all in flight) ----
        if (nnz > 0 && nrows_own > 0) {
            const int items = nnz * nrows_own;
            for (int t = tid; t < items; t += NTHREADS) {
                const int e = t / nrows_own;
                const int k = t - e * nrows_own;
                const unsigned idx = __ldg(&g_eidx[e]);
                const float v = __ldg(&g_eval[e]);
                const unsigned o = idx / (unsigned)IN;   // shifts for pow2 IN
                const unsigned i = idx % (unsigned)IN;
                const size_t r = (size_t)bid + (size_t)k * FB;
                atomicAdd(&out[r * (size_t)OUT + o],
                          v * __ldg(&x[r * (size_t)IN + i]));
            }
        }
    } else {
        // ---- Dense safety net: per-owned-row GEMM (never taken) ----
        for (int k = 0; k < nrows_own; k++) {
            const size_t r = (size_t)bid + (size_t)k * FB;
            float* orow = out + r * (size_t)OUT;
            for (int t = tid; t < OUT; t += NTHREADS)
                orow[t] = __ldg(&bias[t]);
            __syncthreads();
            for (int k0 = 0; k0 < IN; k0 += 4096) {
                const int kc = min(4096, IN - k0);
                for (int t = tid; t < kc; t += NTHREADS)
                    s_buf[t] = x[r * (size_t)IN + k0 + t];
                __syncthreads();
                for (int o = tid; o < OUT; o += NTHREADS) {
                    float acc = 0.f;
                    const float* wrow = weight + (size_t)o * IN + k0;
                    for (int kk = 0; kk < kc; kk++) {
                        float wq = quant1(wrow[kk]);
                        if (wq != 0.f) acc += s_buf[kk] * wq;
                    }
                    orow[o] += acc;
                }
                __syncthreads();
            }
        }
    }

    // Last-finishing block resets the counter for the next graph replay.
    // Every block read g_nnz before incrementing the ticket.
    __syncthreads();
    if (tid == 0) {
        unsigned t = atomicAdd(&g_done, 1u);
        if (t == gridDim.x - 1) { g_done = 0u; g_nnz = 0; }
    }
}

extern "C" void kernel_launch(void* const* d_in, const int* in_sizes, int n_in,
                              void* d_out, int out_size) {
    const float* x      = (const float*)d_in[0];   // [B, IN]
    const float* weight = (const float*)d_in[1];   // [OUT, IN]
    const float* bias   = (const float*)d_in[2];   // [OUT]
    float* out = (float*)d_out;                    // [B, OUT]

    int OUT = in_sizes[2];
    int IN  = in_sizes[1] / OUT;
    int B   = in_sizes[0] / IN;

    k_quant<<<1184, 256>>>(weight, IN, OUT);
    k_fill_fix<<<FBLOCKS, 256>>>(x, weight, bias, out, IN, OUT, B);
}

// round 16
// speedup vs baseline: 1.1738x; 1.1738x over previous
#include <cuda_runtime.h>
#include <cuda_bf16.h>

// ---------------------------------------------------------------------------
// QuantizedLinear: out = x @ quantize(W)^T + bias
// quantize(w) = clamp(ceil(w - 0.5), -4, 3)  (== jnp argmin, first-index ties)
// W = randn*0.1 -> nonzero quantized entries need |w| >= 5 sigma -> nnz ~ 10.
//
// Two-kernel structure (proven):
//   k_quant:    pure-read stream over W, MLP=4 batched loads (at ~6.4 TB/s).
//   k_fill_fix: ONE WAVE (grid=1184, 8/SM), block owns rows {bid, bid+1184,..}
//               (balanced: 7-vs-6 rows, no wave-2 tail). Bias cached in
//               registers -> pure STG.128 stream (R14 body, fill floor).
//               Then fixups on owned rows (no cross-block races).
//               nnz > NNZ_CAP: per-owned-row dense GEMM safety net.
//               Last-finishing block resets the counter for the next replay.
// R15 lesson: cp.async.bulk stores from 1 thread/block serialize (tma=0.2%);
// TMA store path rejected. STG register-bias stream is the best writer.
// ---------------------------------------------------------------------------

#define NNZ_CAP  (1 << 20)   // 1M entries = 8 MB scratch
#define FBLOCKS  1184        // 148 SMs * 8 blocks: exactly one wave
#define NTHREADS 256

__device__ int          g_nnz;               // zero-init; reset by k_fill_fix
__device__ unsigned int g_done;              // ticket for last-block reset
__device__ unsigned int g_eidx[NNZ_CAP];     // o*IN + i
__device__ float        g_eval[NNZ_CAP];     // quantized level (nonzero)

__device__ __forceinline__ float quant1(float w) {
    float q = ceilf(w - 0.5f);               // round-half-down, exact vs argmin
    return fmaxf(-4.0f, fminf(3.0f, q));
}

__device__ __forceinline__ void collect4(float4 w, unsigned base) {
    float q0 = quant1(w.x), q1 = quant1(w.y);
    float q2 = quant1(w.z), q3 = quant1(w.w);
    if ((q0 != 0.f) | (q1 != 0.f) | (q2 != 0.f) | (q3 != 0.f)) {
        if (q0 != 0.f) { int s = atomicAdd(&g_nnz, 1); if (s < NNZ_CAP) { g_eidx[s] = base + 0u; g_eval[s] = q0; } }
        if (q1 != 0.f) { int s = atomicAdd(&g_nnz, 1); if (s < NNZ_CAP) { g_eidx[s] = base + 1u; g_eval[s] = q1; } }
        if (q2 != 0.f) { int s = atomicAdd(&g_nnz, 1); if (s < NNZ_CAP) { g_eidx[s] = base + 2u; g_eval[s] = q2; } }
        if (q3 != 0.f) { int s = atomicAdd(&g_nnz, 1); if (s < NNZ_CAP) { g_eidx[s] = base + 3u; g_eval[s] = q3; } }
    }
}

// ---- Kernel 1: pure-read quantize + collect, MLP=4 batched loads -----------
__global__ void __launch_bounds__(256, 8)
k_quant(const float* __restrict__ weight, int IN, int OUT) {
    const unsigned Wn = (unsigned)OUT * (unsigned)IN;
    const unsigned W4 = Wn >> 2;
    const unsigned gid = blockIdx.x * blockDim.x + threadIdx.x;
    const unsigned stride = gridDim.x * blockDim.x;
    const float4* w4p = reinterpret_cast<const float4*>(weight);

    unsigned t = gid;
    for (; t + 3u * stride < W4; t += 4u * stride) {
        float4 a = __ldcs(&w4p[t]);
        float4 b = __ldcs(&w4p[t + stride]);
        float4 c = __ldcs(&w4p[t + 2u * stride]);
        float4 d = __ldcs(&w4p[t + 3u * stride]);
        collect4(a, t << 2);
        collect4(b, (t + stride) << 2);
        collect4(c, (t + 2u * stride) << 2);
        collect4(d, (t + 3u * stride) << 2);
    }
    for (; t < W4; t += stride)
        collect4(__ldcs(&w4p[t]), t << 2);

    unsigned tail = Wn & 3u;                 // no-op for 4-divisible shapes
    if (gid < tail) {
        unsigned e = (W4 << 2) + gid;
        float q = quant1(weight[e]);
        if (q != 0.f) { int s = atomicAdd(&g_nnz, 1); if (s < NNZ_CAP) { g_eidx[s] = e; g_eval[s] = q; } }
    }
}

// ---- Kernel 2: one-wave owned-rows STG fill + fixup ------------------------
// grid = FBLOCKS, block = 256. Block owns rows r = bid + k*FBLOCKS.
__global__ void __launch_bounds__(256, 8)
k_fill_fix(const float* __restrict__ x,
           const float* __restrict__ weight,
           const float* __restrict__ bias,
           float* __restrict__ out,
           int IN, int OUT, int B) {
    const int nnz = g_nnz;
    const int tid = threadIdx.x;
    const int bid = blockIdx.x;
    const int FB  = gridDim.x;
    const int nrows_own = (bid < B) ? ((B - 1 - bid) / FB + 1) : 0;

    if (nnz <= NNZ_CAP) {
        // ---- Phase A: bias fill, bias cached in registers -> pure STG ----
        const unsigned OUT4 = (unsigned)OUT >> 2;
        const int cpt = (int)(OUT4 / NTHREADS);        // float4 cols / thread
        const bool fast = ((OUT & 3) == 0) && (OUT4 % NTHREADS == 0u) &&
                          (cpt >= 1) && (cpt <= 4);
        if (fast) {
            float4 bc[4];
            const float4* b4 = reinterpret_cast<const float4*>(bias);
            #pragma unroll
            for (int c = 0; c < 4; c++)
                if (c < cpt) bc[c] = __ldg(&b4[tid + c * NTHREADS]);
            float4* o4 = reinterpret_cast<float4*>(out);
            for (int k = 0; k < nrows_own; k++) {
                const size_t r = (size_t)bid + (size_t)k * FB;
                float4* row = o4 + r * OUT4;
                #pragma unroll
                for (int c = 0; c < 4; c++)
                    if (c < cpt) __stcs(&row[tid + c * NTHREADS], bc[c]);
            }
        } else {                              // generic scalar path
            for (int k = 0; k < nrows_own; k++) {
                const size_t r = (size_t)bid + (size_t)k * FB;
                float* ob = out + r * (size_t)OUT;
                for (int t = tid; t < OUT; t += NTHREADS)
                    ob[t] = __ldg(&bias[t]);
            }
        }

        // ---- Phase B: fixups on owned rows (cache-warm lines) ----
        if (nnz > 0 && nrows_own > 0) {
            __syncthreads();   // order fill stores before fixup (block scope)
            const int items = nnz * nrows_own;
            for (int t = tid; t < items; t += NTHREADS) {
                const int e = t / nrows_own;
                const int k = t - e * nrows_own;
                const unsigned idx = __ldg(&g_eidx[e]);
                const float v = __ldg(&g_eval[e]);
                const unsigned o = idx / (unsigned)IN;   // shifts for pow2 IN
                const unsigned i = idx % (unsigned)IN;
                const size_t r = (size_t)bid + (size_t)k * FB;
                atomicAdd(&out[r * (size_t)OUT + o],
                          v * __ldg(&x[r * (size_t)IN + i]));
            }
        }
    } else {
        // ---- Dense safety net: per-owned-row GEMM (never taken) ----
        __shared__ float s_x[4096];
        for (int k = 0; k < nrows_own; k++) {
            const size_t r = (size_t)bid + (size_t)k * FB;
            float* orow = out + r * (size_t)OUT;
            for (int t = tid; t < OUT; t += NTHREADS)
                orow[t] = __ldg(&bias[t]);
            __syncthreads();
            for (int k0 = 0; k0 < IN; k0 += 4096) {
                const int kc = min(4096, IN - k0);
                for (int t = tid; t < kc; t += NTHREADS)
                    s_x[t] = x[r * (size_t)IN + k0 + t];
                __syncthreads();
                for (int o = tid; o < OUT; o += NTHREADS) {
                    float acc = 0.f;
                    const float* wrow = weight + (size_t)o * IN + k0;
                    for (int kk = 0; kk < kc; kk++) {
                        float wq = quant1(wrow[kk]);
                        if (wq != 0.f) acc += s_x[kk] * wq;
                    }
                    orow[o] += acc;
                }
                __syncthreads();
            }
        }
    }

    // Last-finishing block resets the counter for the next graph replay.
    // Every block read g_nnz before incrementing the ticket.
    __syncthreads();
    if (tid == 0) {
        unsigned t = atomicAdd(&g_done, 1u);
        if (t == gridDim.x - 1) { g_done = 0u; g_nnz = 0; }
    }
}

extern "C" void kernel_launch(void* const* d_in, const int* in_sizes, int n_in,
                              void* d_out, int out_size) {
    const float* x      = (const float*)d_in[0];   // [B, IN]
    const float* weight = (const float*)d_in[1];   // [OUT, IN]
    const float* bias   = (const float*)d_in[2];   // [OUT]
    float* out = (float*)d_out;                    // [B, OUT]

    int OUT = in_sizes[2];
    int IN  = in_sizes[1] / OUT;
    int B   = in_sizes[0] / IN;

    k_quant<<<1184, 256>>>(weight, IN, OUT);
    k_fill_fix<<<FBLOCKS, 256>>>(x, weight, bias, out, IN, OUT, B);
}

// round 17
// speedup vs baseline: 1.2187x; 1.0383x over previous
#include <cuda_runtime.h>
#include <cuda_bf16.h>

// ---------------------------------------------------------------------------
// QuantizedLinear: out = x @ quantize(W)^T + bias
// quantize(w) = clamp(ceil(w - 0.5), -4, 3)  (== jnp argmin, first-index ties)
// W = randn*0.1 -> nonzero quantized entries need |w| >= 5 sigma -> nnz ~ 10.
//
// R14 structure (best: 37.4us) + PDL overlap:
//   k_quant:    pure-read stream over W, MLP=4 batched loads (~6.4 TB/s, cap).
//               Triggers programmatic launch completion AT ENTRY so the fill
//               kernel's independent bias-fill overlaps the W read stream.
//   k_fill_fix: grid 2048, block owns 4 contiguous rows (proven fill floor).
//               Phase A: register-bias pure STG.128 fill (independent of quant)
//               -> cudaGridDependencySynchronize() -> Phase B fixups on owned
//               rows (cache-warm, no cross-block races).
//               nnz > NNZ_CAP: owned-rows dense GEMM safety net (never taken).
//               Last-finishing block resets the counter for the next replay.
// Ledger: TMA store rejected (R15, tma=0.2%); in-kernel role overlap rejected
// (R12 75.8, R13 55.3); one-wave strided ownership rejected (R16 39.0).
// ---------------------------------------------------------------------------

#define NNZ_CAP (1 << 20)   // 1M entries = 8 MB scratch
#define ROWS_PB 4           // rows owned per k_fill_fix block

__device__ int          g_nnz;               // zero-init; reset by k_fill_fix
__device__ unsigned int g_done;              // ticket for last-block reset
__device__ unsigned int g_eidx[NNZ_CAP];     // o*IN + i
__device__ float        g_eval[NNZ_CAP];     // quantized level (nonzero)

__device__ __forceinline__ float quant1(float w) {
    float q = ceilf(w - 0.5f);               // round-half-down, exact vs argmin
    return fmaxf(-4.0f, fminf(3.0f, q));
}

__device__ __forceinline__ void collect4(float4 w, unsigned base) {
    float q0 = quant1(w.x), q1 = quant1(w.y);
    float q2 = quant1(w.z), q3 = quant1(w.w);
    if ((q0 != 0.f) | (q1 != 0.f) | (q2 != 0.f) | (q3 != 0.f)) {
        if (q0 != 0.f) { int s = atomicAdd(&g_nnz, 1); if (s < NNZ_CAP) { g_eidx[s] = base + 0u; g_eval[s] = q0; } }
        if (q1 != 0.f) { int s = atomicAdd(&g_nnz, 1); if (s < NNZ_CAP) { g_eidx[s] = base + 1u; g_eval[s] = q1; } }
        if (q2 != 0.f) { int s = atomicAdd(&g_nnz, 1); if (s < NNZ_CAP) { g_eidx[s] = base + 2u; g_eval[s] = q2; } }
        if (q3 != 0.f) { int s = atomicAdd(&g_nnz, 1); if (s < NNZ_CAP) { g_eidx[s] = base + 3u; g_eval[s] = q3; } }
    }
}

// ---- Kernel 1: pure-read quantize + collect, MLP=4 batched loads -----------
__global__ void __launch_bounds__(256, 8)
k_quant(const float* __restrict__ weight, int IN, int OUT) {
    // Allow the dependent fill kernel to start now: its Phase A (bias fill)
    // is independent; it gates on grid completion before reading g_nnz.
    cudaTriggerProgrammaticLaunchCompletion();

    const unsigned Wn = (unsigned)OUT * (unsigned)IN;
    const unsigned W4 = Wn >> 2;
    const unsigned gid = blockIdx.x * blockDim.x + threadIdx.x;
    const unsigned stride = gridDim.x * blockDim.x;
    const float4* w4p = reinterpret_cast<const float4*>(weight);

    unsigned t = gid;
    for (; t + 3u * stride < W4; t += 4u * stride) {
        float4 a = __ldcs(&w4p[t]);
        float4 b = __ldcs(&w4p[t + stride]);
        float4 c = __ldcs(&w4p[t + 2u * stride]);
        float4 d = __ldcs(&w4p[t + 3u * stride]);
        collect4(a, t << 2);
        collect4(b, (t + stride) << 2);
        collect4(c, (t + 2u * stride) << 2);
        collect4(d, (t + 3u * stride) << 2);
    }
    for (; t < W4; t += stride)
        collect4(__ldcs(&w4p[t]), t << 2);

    unsigned tail = Wn & 3u;                 // no-op for 4-divisible shapes
    if (gid < tail) {
        unsigned e = (W4 << 2) + gid;
        float q = quant1(weight[e]);
        if (q != 0.f) { int s = atomicAdd(&g_nnz, 1); if (s < NNZ_CAP) { g_eidx[s] = e; g_eval[s] = q; } }
    }
}

// ---- Kernel 2: owned-rows fill (register bias, pure stores) + fixup --------
// grid = ceil(B / ROWS_PB), block = 256. Block b owns rows [b*R, b*R+R).
__global__ void __launch_bounds__(256, 8)
k_fill_fix(const float* __restrict__ x,
           const float* __restrict__ weight,
           const float* __restrict__ bias,
           float* __restrict__ out,
           int IN, int OUT, int B) {
    const int r0 = blockIdx.x * ROWS_PB;
    const int nrows = min(ROWS_PB, B - r0);
    const int tid = threadIdx.x;

    // ---- Phase A: bias fill (independent of quant results) ----
    const unsigned OUT4 = (unsigned)OUT >> 2;
    const int cpt = (int)(OUT4 / 256u);                // float4 cols / thread
    const bool fast = (nrows == ROWS_PB) && ((OUT & 3) == 0) &&
                      (OUT4 % 256u == 0u) && (cpt >= 1) && (cpt <= 4);
    if (fast) {
        float4 bc[4];
        const float4* b4 = reinterpret_cast<const float4*>(bias);
        #pragma unroll
        for (int c = 0; c < 4; c++)
            if (c < cpt) bc[c] = __ldg(&b4[tid + c * 256]);
        float4* o4 = reinterpret_cast<float4*>(out) + (size_t)r0 * OUT4;
        #pragma unroll
        for (int r = 0; r < ROWS_PB; r++) {
            float4* row = o4 + (size_t)r * OUT4;
            #pragma unroll
            for (int c = 0; c < 4; c++)
                if (c < cpt) __stcs(&row[tid + c * 256], bc[c]);
        }
    } else {                                  // generic scalar path (tails)
        const unsigned n = (unsigned)nrows * (unsigned)OUT;
        float* ob = out + (size_t)r0 * OUT;
        for (unsigned t = tid; t < n; t += blockDim.x)
            ob[t] = __ldg(&bias[t % (unsigned)OUT]);
    }

    // ---- Wait for k_quant grid completion (PDL); then entries visible ----
    cudaGridDependencySynchronize();
    __syncthreads();                         // order fill stores before fixup
    const int nnz = *((volatile int*)&g_nnz);

    if (nnz <= NNZ_CAP) {
        // ---- Phase B: fixups for owned rows; lines are cache-warm ----
        if (nnz > 0) {
            const int items = nnz * nrows;
            for (int t = tid; t < items; t += blockDim.x) {
                const int e = t / nrows;
                const int r = t - e * nrows;
                const unsigned idx = __ldg(&g_eidx[e]);
                const float v = __ldg(&g_eval[e]);
                const unsigned o = idx / (unsigned)IN;   // shifts for pow2 IN
                const unsigned i = idx % (unsigned)IN;
                const int b = r0 + r;
                atomicAdd(&out[(size_t)b * OUT + o],
                          v * __ldg(&x[(size_t)b * IN + i]));
            }
        }
    } else {
        // ---- Dense safety net: owned-rows GEMM accumulating onto the
        //      already-written bias (never taken on this dataset) ----
        __shared__ float xs[ROWS_PB][1024];
        for (int k0 = 0; k0 < IN; k0 += 1024) {
            const int kc = min(1024, IN - k0);
            __syncthreads();
            for (int t = tid; t < nrows * kc; t += blockDim.x) {
                int r = t / kc, kk = t - r * kc;
                xs[r][kk] = x[(size_t)(r0 + r) * IN + k0 + kk];
            }
            __syncthreads();
            for (int o = tid; o < OUT; o += blockDim.x) {
                float acc[ROWS_PB];
                #pragma unroll
                for (int r = 0; r < ROWS_PB; r++) acc[r] = 0.f;
                const float* wrow = weight + (size_t)o * IN + k0;
                for (int kk = 0; kk < kc; kk++) {
                    float wq = quant1(wrow[kk]);
                    if (wq != 0.f) {
                        #pragma unroll
                        for (int r = 0; r < ROWS_PB; r++)
                            acc[r] += xs[r][kk] * wq;
                    }
                }
                for (int r = 0; r < nrows; r++)
                    out[(size_t)(r0 + r) * OUT + o] += acc[r];
            }
        }
    }

    // Last-finishing block resets the counter for the next graph replay.
    // Every block read g_nnz before incrementing the ticket.
    __syncthreads();
    if (tid == 0) {
        unsigned t = atomicAdd(&g_done, 1u);
        if (t == gridDim.x - 1) { g_done = 0u; g_nnz = 0; }
    }
}

extern "C" void kernel_launch(void* const* d_in, const int* in_sizes, int n_in,
                              void* d_out, int out_size) {
    const float* x      = (const float*)d_in[0];   // [B, IN]
    const float* weight = (const float*)d_in[1];   // [OUT, IN]
    const float* bias   = (const float*)d_in[2];   // [OUT]
    float* out = (float*)d_out;                    // [B, OUT]

    int OUT = in_sizes[2];
    int IN  = in_sizes[1] / OUT;
    int B   = in_sizes[0] / IN;

    k_quant<<<1184, 256>>>(weight, IN, OUT);

    // Fill kernel launched with Programmatic Stream Serialization: it may
    // start as soon as k_quant triggers (at entry), overlapping the bias-fill
    // write stream with the W read stream; fixups gate on grid completion
    // via cudaGridDependencySynchronize() inside the kernel.
    int fblocks = (B + ROWS_PB - 1) / ROWS_PB;     // 2048 for B=8192
    cudaLaunchConfig_t cfg = {};
    cfg.gridDim = dim3((unsigned)fblocks, 1, 1);
    cfg.blockDim = dim3(256, 1, 1);
    cfg.dynamicSmemBytes = 0;
    cfg.stream = 0;
    cudaLaunchAttribute attrs[1];
    attrs[0].id = cudaLaunchAttributeProgrammaticStreamSerialization;
    attrs[0].val.programmaticStreamSerializationAllowed = 1;
    cfg.attrs = attrs;
    cfg.numAttrs = 1;
    cudaLaunchKernelEx(&cfg, k_fill_fix, x, weight, bias, out, IN, OUT, B);
}